// round 11
// baseline (speedup 1.0000x reference)
#include <cuda_runtime.h>
#include <cuda_fp16.h>
#include <cstdint>

#define NN    50000
#define EE    800000
#define ETOT  850000          // EE + NN self loops
#define INCH  128
#define HC    256             // 4 heads * 64

// ---------------- static scratch ----------------
__device__ __align__(16) __half2 g_hh[(size_t)NN * (HC / 2)]; // layer-1 features fp16
__device__ float g_as[NN * 4];
__device__ float g_ad[NN * 4];
__device__ float g_z[NN];
__device__ int   g_deg[NN];
__device__ int   g_off[NN];
__device__ int   g_cur[NN];
__device__ int   g_csrc[ETOT];
__device__ int   g_total;

// ---------------- GEMM tiling ----------------
#define GEMM_GRID 296            // 2 CTAs/SM on 148 SMs, fully resident
#define NCHUNK 782               // ceil(NN/64)
#define PADB2 264                // B row pitch (halves)
#define PADA2 136                // A row pitch (halves)
#define SMEM_B_BYTES (128 * PADB2 * 2)             // 67584
#define SMEM_A_BYTES (64 * PADA2 * 2)              // 17408 per buffer
#define SMEM_TOTAL_GEMM (SMEM_B_BYTES + 2 * SMEM_A_BYTES)   // 102400

__global__ void k_gemm_mma(const float*, const float*, const float*, const float*);

// ---------------- streams/events + symbol addresses ----------------
static cudaStream_t g_s2;
static cudaEvent_t g_evFork, g_evJoin;
static void* g_deg_addr;
static void* g_total_addr;
namespace {
struct SInit {
    SInit() {
        cudaStreamCreateWithFlags(&g_s2, cudaStreamNonBlocking);
        cudaEventCreateWithFlags(&g_evFork, cudaEventDisableTiming);
        cudaEventCreateWithFlags(&g_evJoin, cudaEventDisableTiming);
        cudaGetSymbolAddress(&g_deg_addr, g_deg);
        cudaGetSymbolAddress(&g_total_addr, g_total);
        cudaFuncSetAttribute(k_gemm_mma, cudaFuncAttributeMaxDynamicSharedMemorySize,
                             SMEM_TOTAL_GEMM);
    }
};
SInit sinit_;
}

// ---------------- CSR build ----------------
__global__ void k_count(const int4* __restrict__ eid4) {
    int e = blockIdx.x * blockDim.x + threadIdx.x;
    if (e < EE / 4) {
        int4 d = eid4[e];
        atomicAdd(&g_deg[d.x], 1);
        atomicAdd(&g_deg[d.y], 1);
        atomicAdd(&g_deg[d.z], 1);
        atomicAdd(&g_deg[d.w], 1);
    }
}

__global__ void k_offsets() {
    int i = blockIdx.x * blockDim.x + threadIdx.x;
    int lane = threadIdx.x & 31;
    int d = (i < NN) ? g_deg[i] + 1 : 0;   // +1 self loop
    int pre = d;
#pragma unroll
    for (int o = 1; o < 32; o <<= 1) {
        int t = __shfl_up_sync(0xFFFFFFFFu, pre, o);
        if (lane >= o) pre += t;
    }
    int base = 0;
    if (lane == 31) base = atomicAdd(&g_total, pre);
    base = __shfl_sync(0xFFFFFFFFu, base, 31);
    if (i < NN) {
        int off = base + pre - d;
        g_deg[i] = d;
        g_off[i] = off;
        g_cur[i] = off;
    }
}

__global__ void k_scatter(const int* __restrict__ ei) {
    int e4 = blockIdx.x * blockDim.x + threadIdx.x;
    int nvec = EE / 4;
    if (e4 < nvec) {
        int4 s = ((const int4*)ei)[e4];
        int4 d = ((const int4*)(ei + EE))[e4];
        g_csrc[atomicAdd(&g_cur[d.x], 1)] = s.x;
        g_csrc[atomicAdd(&g_cur[d.y], 1)] = s.y;
        g_csrc[atomicAdd(&g_cur[d.z], 1)] = s.z;
        g_csrc[atomicAdd(&g_cur[d.w], 1)] = s.w;
    } else {
        int n = e4 - nvec;
        if (n < NN) g_csrc[atomicAdd(&g_cur[n], 1)] = n;
    }
}

// ---------------- tensor-core GEMM: persistent, B resident, A double-buffered ----------------
__device__ __forceinline__ void ldsm4(uint32_t& r0, uint32_t& r1, uint32_t& r2, uint32_t& r3,
                                      const __half* p) {
    uint32_t a = (uint32_t)__cvta_generic_to_shared(p);
    asm volatile("ldmatrix.sync.aligned.m8n8.x4.shared.b16 {%0,%1,%2,%3},[%4];"
                 : "=r"(r0), "=r"(r1), "=r"(r2), "=r"(r3) : "r"(a));
}
__device__ __forceinline__ void ldsm4t(uint32_t& r0, uint32_t& r1, uint32_t& r2, uint32_t& r3,
                                       const __half* p) {
    uint32_t a = (uint32_t)__cvta_generic_to_shared(p);
    asm volatile("ldmatrix.sync.aligned.m8n8.x4.trans.shared.b16 {%0,%1,%2,%3},[%4];"
                 : "=r"(r0), "=r"(r1), "=r"(r2), "=r"(r3) : "r"(a));
}
__device__ __forceinline__ void mma16816(float* c, const uint32_t* a, const uint32_t* b) {
    asm volatile(
        "mma.sync.aligned.m16n8k16.row.col.f32.f16.f16.f32 "
        "{%0,%1,%2,%3},{%4,%5,%6,%7},{%8,%9},{%0,%1,%2,%3};"
        : "+f"(c[0]), "+f"(c[1]), "+f"(c[2]), "+f"(c[3])
        : "r"(a[0]), "r"(a[1]), "r"(a[2]), "r"(a[3]), "r"(b[0]), "r"(b[1]));
}

__device__ __forceinline__ void load_a_chunk(const float* __restrict__ x,
                                             __half* __restrict__ Adst, int bm, int tid) {
    for (int idx = tid; idx < 64 * 16; idx += 256) {
        int row = idx >> 4;
        int colh = (idx & 15) * 8;
        int grow = bm + row; if (grow >= NN) grow = NN - 1;
        const float4* xp = (const float4*)&x[(size_t)grow * INCH + colh];
        float4 v0 = xp[0], v1 = xp[1];
        float f[8] = {v0.x, v0.y, v0.z, v0.w, v1.x, v1.y, v1.z, v1.w};
        __half h[8];
#pragma unroll
        for (int q = 0; q < 8; q++) h[q] = __float2half_rn(f[q]);
        *(uint4*)&Adst[row * PADA2 + colh] = *(uint4*)h;
    }
}

__global__ __launch_bounds__(256, 2) void k_gemm_mma(const float* __restrict__ x,
                                                     const float* __restrict__ W,
                                                     const float* __restrict__ att_s,
                                                     const float* __restrict__ att_d) {
    extern __shared__ char smem[];
    __half* Bs = (__half*)smem;                               // [128][PADB2]
    __half* Abuf[2] = {(__half*)(smem + SMEM_B_BYTES),
                       (__half*)(smem + SMEM_B_BYTES + SMEM_A_BYTES)};
    const int tid = threadIdx.x;
    const int lane = tid & 31;
    const int w = tid >> 5;
    const int wm = w & 1;
    const int wncol = w >> 1;

    // load whole B (128x256) fp32 -> fp16 once
    for (int idx = tid; idx < 128 * 32; idx += 256) {
        int row = idx >> 5;
        int colh = (idx & 31) * 8;
        const float4* wp = (const float4*)&W[(size_t)row * HC + colh];
        float4 v0 = wp[0], v1 = wp[1];
        float f[8] = {v0.x, v0.y, v0.z, v0.w, v1.x, v1.y, v1.z, v1.w};
        __half h[8];
#pragma unroll
        for (int q = 0; q < 8; q++) h[q] = __float2half_rn(f[q]);
        *(uint4*)&Bs[row * PADB2 + colh] = *(uint4*)h;
    }

    const int lrow = lane & 7;
    const int lhalf = (lane & 8) ? 8 : 0;
    const int lq = (lane & 16) ? 8 : 0;
    const int gid = lane >> 2, tig = lane & 3;

    float aS[8][2], aD[8][2];
#pragma unroll
    for (int j = 0; j < 8; j++) {
        int col = wncol * 64 + j * 8 + tig * 2;
        aS[j][0] = att_s[col];     aS[j][1] = att_s[col + 1];
        aD[j][0] = att_d[col];     aD[j][1] = att_d[col + 1];
    }

    // preload first chunk
    if (blockIdx.x < NCHUNK) load_a_chunk(x, Abuf[0], blockIdx.x * 64, tid);
    __syncthreads();

    int buf = 0;
    for (int c = blockIdx.x; c < NCHUNK; c += GEMM_GRID, buf ^= 1) {
        const int bm = c * 64;
        // prefetch next chunk into other buffer (overlaps with mma below)
        if (c + GEMM_GRID < NCHUNK)
            load_a_chunk(x, Abuf[buf ^ 1], (c + GEMM_GRID) * 64, tid);

        const __half* Ah = Abuf[buf];
        float cacc[2][8][4];
#pragma unroll
        for (int i = 0; i < 2; i++)
#pragma unroll
            for (int j = 0; j < 8; j++)
#pragma unroll
                for (int q = 0; q < 4; q++) cacc[i][j][q] = 0.f;

#pragma unroll
        for (int ksi = 0; ksi < 8; ksi++) {
            const int ks = ksi * 16;
            uint32_t bf[8][2];
#pragma unroll
            for (int jj = 0; jj < 4; jj++) {
                int brow = ks + lrow + lhalf;
                int bcol = wncol * 64 + jj * 16 + lq;
                ldsm4t(bf[2 * jj][0], bf[2 * jj][1], bf[2 * jj + 1][0], bf[2 * jj + 1][1],
                       &Bs[brow * PADB2 + bcol]);
            }
#pragma unroll
            for (int i = 0; i < 2; i++) {
                uint32_t af[4];
                int arow = wm * 32 + i * 16 + lrow + lhalf;
                ldsm4(af[0], af[1], af[2], af[3], &Ah[arow * PADA2 + ks + lq]);
#pragma unroll
                for (int j = 0; j < 8; j++) mma16816(cacc[i][j], af, bf[j]);
            }
        }

        // epilogue: store h fp16 + fused dots
#pragma unroll
        for (int i = 0; i < 2; i++) {
            int r0 = bm + wm * 32 + i * 16 + gid;
            int r1 = r0 + 8;
            int h2i = wncol * 32 + tig;
            if (r0 < NN) {
#pragma unroll
                for (int j = 0; j < 8; j++)
                    g_hh[(size_t)r0 * 128 + h2i + j * 4] =
                        __floats2half2_rn(cacc[i][j][0], cacc[i][j][1]);
            }
            if (r1 < NN) {
#pragma unroll
                for (int j = 0; j < 8; j++)
                    g_hh[(size_t)r1 * 128 + h2i + j * 4] =
                        __floats2half2_rn(cacc[i][j][2], cacc[i][j][3]);
            }
            float s0 = 0.f, s1 = 0.f, d0 = 0.f, d1 = 0.f;
#pragma unroll
            for (int j = 0; j < 8; j++) {
                s0 += cacc[i][j][0] * aS[j][0] + cacc[i][j][1] * aS[j][1];
                s1 += cacc[i][j][2] * aS[j][0] + cacc[i][j][3] * aS[j][1];
                d0 += cacc[i][j][0] * aD[j][0] + cacc[i][j][1] * aD[j][1];
                d1 += cacc[i][j][2] * aD[j][0] + cacc[i][j][3] * aD[j][1];
            }
#pragma unroll
            for (int o = 1; o <= 2; o <<= 1) {
                s0 += __shfl_xor_sync(0xFFFFFFFFu, s0, o);
                s1 += __shfl_xor_sync(0xFFFFFFFFu, s1, o);
                d0 += __shfl_xor_sync(0xFFFFFFFFu, d0, o);
                d1 += __shfl_xor_sync(0xFFFFFFFFu, d1, o);
            }
            if (tig == 0) {
                if (r0 < NN) { g_as[r0 * 4 + wncol] = s0; g_ad[r0 * 4 + wncol] = d0; }
                if (r1 < NN) { g_as[r1 * 4 + wncol] = s1; g_ad[r1 * 4 + wncol] = d1; }
            }
        }
        __syncthreads();   // next iter writes/reads buffers safely
    }
}

__device__ __forceinline__ float leaky(float x) { return x > 0.f ? x : 0.2f * x; }

// ---------------- layer-1 softmax+aggregation + fused layer-2 projection ----------------
// Persistent interleaved warps: warp g handles nodes g, g+W, ... (degree-averaging)
__device__ __forceinline__ void agg_edge1(float asv, uint4 r, float advh,
                                          float* a, float& den) {
    float w = __expf(leaky(asv + advh));
    den += w;
    float2 f0 = __half22float2(*(__half2*)&r.x);
    float2 f1 = __half22float2(*(__half2*)&r.y);
    float2 f2 = __half22float2(*(__half2*)&r.z);
    float2 f3 = __half22float2(*(__half2*)&r.w);
    a[0] += w * f0.x; a[1] += w * f0.y;
    a[2] += w * f1.x; a[3] += w * f1.y;
    a[4] += w * f2.x; a[5] += w * f2.y;
    a[6] += w * f3.x; a[7] += w * f3.y;
}

#define AGG_BLOCKS 592   // 592 * 8 = 4736 warps ≈ 10.5 nodes/warp

__global__ void k_agg1(const float* __restrict__ bias,
                       const float* __restrict__ W2) {
    int warp0 = (blockIdx.x * blockDim.x + threadIdx.x) >> 5;
    int nwarps = (gridDim.x * blockDim.x) >> 5;
    int lane = threadIdx.x & 31;
    int head = lane >> 3;
    int colb = lane * 8;
    const float4* bv = (const float4*)(bias + colb);
    float4 b0 = bv[0], b1 = bv[1];
    const float4* wv = (const float4*)(W2 + colb);
    float4 w0 = wv[0], w1 = wv[1];

    for (int gw = warp0; gw < NN; gw += nwarps) {
        int beg = g_off[gw];
        int end = beg + g_deg[gw];
        float advh = g_ad[gw * 4 + head];

        float a[8];
#pragma unroll
        for (int j = 0; j < 8; j++) a[j] = 0.f;
        float den = 0.f;

        int p = beg;
        for (; p + 4 <= end; p += 4) {
            int s0 = g_csrc[p], s1 = g_csrc[p + 1], s2 = g_csrc[p + 2], s3 = g_csrc[p + 3];
            float as0 = g_as[s0 * 4 + head];
            float as1 = g_as[s1 * 4 + head];
            float as2 = g_as[s2 * 4 + head];
            float as3 = g_as[s3 * 4 + head];
            uint4 r0 = *(const uint4*)(g_hh + (size_t)s0 * 128 + lane * 4);
            uint4 r1 = *(const uint4*)(g_hh + (size_t)s1 * 128 + lane * 4);
            uint4 r2 = *(const uint4*)(g_hh + (size_t)s2 * 128 + lane * 4);
            uint4 r3 = *(const uint4*)(g_hh + (size_t)s3 * 128 + lane * 4);
            agg_edge1(as0, r0, advh, a, den);
            agg_edge1(as1, r1, advh, a, den);
            agg_edge1(as2, r2, advh, a, den);
            agg_edge1(as3, r3, advh, a, den);
        }
        for (; p < end; p++) {
            int s = g_csrc[p];
            float asv = g_as[s * 4 + head];
            uint4 r = *(const uint4*)(g_hh + (size_t)s * 128 + lane * 4);
            agg_edge1(asv, r, advh, a, den);
        }

        float inv = 1.f / den;
        float pr = 0.f, t;
        t = a[0] * inv + b0.x; t = t > 0.f ? t : expm1f(t); pr += t * w0.x;
        t = a[1] * inv + b0.y; t = t > 0.f ? t : expm1f(t); pr += t * w0.y;
        t = a[2] * inv + b0.z; t = t > 0.f ? t : expm1f(t); pr += t * w0.z;
        t = a[3] * inv + b0.w; t = t > 0.f ? t : expm1f(t); pr += t * w0.w;
        t = a[4] * inv + b1.x; t = t > 0.f ? t : expm1f(t); pr += t * w1.x;
        t = a[5] * inv + b1.y; t = t > 0.f ? t : expm1f(t); pr += t * w1.y;
        t = a[6] * inv + b1.z; t = t > 0.f ? t : expm1f(t); pr += t * w1.z;
        t = a[7] * inv + b1.w; t = t > 0.f ? t : expm1f(t); pr += t * w1.w;
#pragma unroll
        for (int o = 16; o; o >>= 1) pr += __shfl_xor_sync(0xFFFFFFFFu, pr, o);
        if (lane == 0) g_z[gw] = pr;
    }
}

// ---------------- layer-2 softmax + aggregation ----------------
__global__ void k_agg2(const float* __restrict__ att_s2,
                       const float* __restrict__ att_d2,
                       const float* __restrict__ bias2,
                       float* __restrict__ out) {
    int warp0 = (blockIdx.x * blockDim.x + threadIdx.x) >> 5;
    int nwarps = (gridDim.x * blockDim.x) >> 5;
    int lane = threadIdx.x & 31;
    float atts = att_s2[0], attd = att_d2[0];
    float b2 = bias2[0];

    for (int gw = warp0; gw < NN; gw += nwarps) {
        int beg = g_off[gw];
        int end = beg + g_deg[gw];
        float adv = g_z[gw] * attd;

        float den = 0.f, acc = 0.f;
        for (int p = beg + lane; p < end; p += 32) {
            int s = g_csrc[p];
            float zs = g_z[s];
            float w = __expf(leaky(zs * atts + adv));
            den += w;
            acc += w * zs;
        }
#pragma unroll
        for (int o = 16; o; o >>= 1) {
            den += __shfl_xor_sync(0xFFFFFFFFu, den, o);
            acc += __shfl_xor_sync(0xFFFFFFFFu, acc, o);
        }
        if (lane == 0) out[gw] = acc / den + b2;
    }
}

// ---------------- launch ----------------
extern "C" void kernel_launch(void* const* d_in, const int* in_sizes, int n_in,
                              void* d_out, int out_size) {
    const float* x     = (const float*)d_in[0];
    const int*   ei    = (const int*)d_in[1];
    const float* W1    = (const float*)d_in[2];
    const float* atts1 = (const float*)d_in[3];
    const float* attd1 = (const float*)d_in[4];
    const float* bias1 = (const float*)d_in[5];
    const float* W2    = (const float*)d_in[6];
    const float* atts2 = (const float*)d_in[7];
    const float* attd2 = (const float*)d_in[8];
    const float* bias2 = (const float*)d_in[9];
    float* out = (float*)d_out;
    (void)in_sizes; (void)n_in; (void)out_size;

    cudaFuncSetAttribute(k_gemm_mma, cudaFuncAttributeMaxDynamicSharedMemorySize,
                         SMEM_TOTAL_GEMM);

    // fork: CSR chain on g_s2, GEMM on main stream
    cudaEventRecord(g_evFork, 0);
    cudaStreamWaitEvent(g_s2, g_evFork, 0);

    cudaMemsetAsync(g_deg_addr, 0, NN * sizeof(int), g_s2);
    cudaMemsetAsync(g_total_addr, 0, sizeof(int), g_s2);
    k_count<<<(EE / 4 + 255) / 256, 256, 0, g_s2>>>((const int4*)(ei + EE));
    k_offsets<<<(NN + 255) / 256, 256, 0, g_s2>>>();
    k_scatter<<<(EE / 4 + NN + 255) / 256, 256, 0, g_s2>>>(ei);
    cudaEventRecord(g_evJoin, g_s2);

    k_gemm_mma<<<GEMM_GRID, 256, SMEM_TOTAL_GEMM>>>(x, W1, atts1, attd1);

    cudaStreamWaitEvent(0, g_evJoin, 0);

    k_agg1<<<AGG_BLOCKS, 256>>>(bias1, W2);
    k_agg2<<<AGG_BLOCKS, 256>>>(atts2, attd2, bias2, out);
}

// round 12
// speedup vs baseline: 1.1038x; 1.1038x over previous
#include <cuda_runtime.h>
#include <cuda_fp16.h>
#include <cstdint>

#define NN    50000
#define EE    800000
#define ETOT  850000          // EE + NN self loops
#define INCH  128
#define HC    256             // 4 heads * 64

// ---------------- static scratch ----------------
__device__ __align__(16) __half2 g_hh[(size_t)NN * (HC / 2)]; // layer-1 features fp16
__device__ float g_as[NN * 4];
__device__ float g_ad[NN * 4];
__device__ float g_z[NN];
__device__ int   g_deg[NN];
__device__ int   g_off[NN];
__device__ int   g_cur[NN];
__device__ int   g_csrc[ETOT];
__device__ int   g_total;

// ---------------- GEMM tiling ----------------
#define GEMM_GRID 296            // 2 CTAs/SM, fully resident persistent grid
#define NCHUNK 782               // ceil(NN/64)
#define PADB2 264                // B row pitch (halves)
#define PADA2 136                // A row pitch (halves)
#define SMEM_B_BYTES (128 * PADB2 * 2)             // 67584
#define SMEM_A_BYTES (64 * PADA2 * 2)              // 17408 per buffer
#define SMEM_TOTAL_GEMM (SMEM_B_BYTES + 2 * SMEM_A_BYTES)   // 102400

__global__ void k_gemm_mma(const float*, const float*, const float*, const float*);

// ---------------- streams/events + symbol addresses ----------------
static cudaStream_t g_s2;
static cudaEvent_t g_evFork, g_evJoin;
static void* g_deg_addr;
static void* g_total_addr;
namespace {
struct SInit {
    SInit() {
        cudaStreamCreateWithFlags(&g_s2, cudaStreamNonBlocking);
        cudaEventCreateWithFlags(&g_evFork, cudaEventDisableTiming);
        cudaEventCreateWithFlags(&g_evJoin, cudaEventDisableTiming);
        cudaGetSymbolAddress(&g_deg_addr, g_deg);
        cudaGetSymbolAddress(&g_total_addr, g_total);
        cudaFuncSetAttribute(k_gemm_mma, cudaFuncAttributeMaxDynamicSharedMemorySize,
                             SMEM_TOTAL_GEMM);
    }
};
SInit sinit_;
}

// ---------------- CSR build ----------------
__global__ void k_count(const int4* __restrict__ eid4) {
    int e = blockIdx.x * blockDim.x + threadIdx.x;
    if (e < EE / 4) {
        int4 d = eid4[e];
        atomicAdd(&g_deg[d.x], 1);
        atomicAdd(&g_deg[d.y], 1);
        atomicAdd(&g_deg[d.z], 1);
        atomicAdd(&g_deg[d.w], 1);
    }
}

__global__ void k_offsets() {
    int i = blockIdx.x * blockDim.x + threadIdx.x;
    int lane = threadIdx.x & 31;
    int d = (i < NN) ? g_deg[i] + 1 : 0;   // +1 self loop
    int pre = d;
#pragma unroll
    for (int o = 1; o < 32; o <<= 1) {
        int t = __shfl_up_sync(0xFFFFFFFFu, pre, o);
        if (lane >= o) pre += t;
    }
    int base = 0;
    if (lane == 31) base = atomicAdd(&g_total, pre);
    base = __shfl_sync(0xFFFFFFFFu, base, 31);
    if (i < NN) {
        int off = base + pre - d;
        g_deg[i] = d;
        g_off[i] = off;
        g_cur[i] = off;
    }
}

__global__ void k_scatter(const int* __restrict__ ei) {
    int e4 = blockIdx.x * blockDim.x + threadIdx.x;
    int nvec = EE / 4;
    if (e4 < nvec) {
        int4 s = ((const int4*)ei)[e4];
        int4 d = ((const int4*)(ei + EE))[e4];
        g_csrc[atomicAdd(&g_cur[d.x], 1)] = s.x;
        g_csrc[atomicAdd(&g_cur[d.y], 1)] = s.y;
        g_csrc[atomicAdd(&g_cur[d.z], 1)] = s.z;
        g_csrc[atomicAdd(&g_cur[d.w], 1)] = s.w;
    } else {
        int n = e4 - nvec;
        if (n < NN) g_csrc[atomicAdd(&g_cur[n], 1)] = n;
    }
}

// ---------------- tensor-core GEMM: persistent, B resident, A double-buffered ----------------
__device__ __forceinline__ void ldsm4(uint32_t& r0, uint32_t& r1, uint32_t& r2, uint32_t& r3,
                                      const __half* p) {
    uint32_t a = (uint32_t)__cvta_generic_to_shared(p);
    asm volatile("ldmatrix.sync.aligned.m8n8.x4.shared.b16 {%0,%1,%2,%3},[%4];"
                 : "=r"(r0), "=r"(r1), "=r"(r2), "=r"(r3) : "r"(a));
}
__device__ __forceinline__ void ldsm4t(uint32_t& r0, uint32_t& r1, uint32_t& r2, uint32_t& r3,
                                       const __half* p) {
    uint32_t a = (uint32_t)__cvta_generic_to_shared(p);
    asm volatile("ldmatrix.sync.aligned.m8n8.x4.trans.shared.b16 {%0,%1,%2,%3},[%4];"
                 : "=r"(r0), "=r"(r1), "=r"(r2), "=r"(r3) : "r"(a));
}
__device__ __forceinline__ void mma16816(float* c, const uint32_t* a, const uint32_t* b) {
    asm volatile(
        "mma.sync.aligned.m16n8k16.row.col.f32.f16.f16.f32 "
        "{%0,%1,%2,%3},{%4,%5,%6,%7},{%8,%9},{%0,%1,%2,%3};"
        : "+f"(c[0]), "+f"(c[1]), "+f"(c[2]), "+f"(c[3])
        : "r"(a[0]), "r"(a[1]), "r"(a[2]), "r"(a[3]), "r"(b[0]), "r"(b[1]));
}

__device__ __forceinline__ void load_a_chunk(const float* __restrict__ x,
                                             __half* __restrict__ Adst, int bm, int tid) {
    for (int idx = tid; idx < 64 * 16; idx += 256) {
        int row = idx >> 4;
        int colh = (idx & 15) * 8;
        int grow = bm + row; if (grow >= NN) grow = NN - 1;
        const float4* xp = (const float4*)&x[(size_t)grow * INCH + colh];
        float4 v0 = xp[0], v1 = xp[1];
        float f[8] = {v0.x, v0.y, v0.z, v0.w, v1.x, v1.y, v1.z, v1.w};
        __half h[8];
#pragma unroll
        for (int q = 0; q < 8; q++) h[q] = __float2half_rn(f[q]);
        *(uint4*)&Adst[row * PADA2 + colh] = *(uint4*)h;
    }
}

__global__ __launch_bounds__(256, 2) void k_gemm_mma(const float* __restrict__ x,
                                                     const float* __restrict__ W,
                                                     const float* __restrict__ att_s,
                                                     const float* __restrict__ att_d) {
    extern __shared__ char smem[];
    __half* Bs = (__half*)smem;                               // [128][PADB2]
    __half* Abuf[2] = {(__half*)(smem + SMEM_B_BYTES),
                       (__half*)(smem + SMEM_B_BYTES + SMEM_A_BYTES)};
    const int tid = threadIdx.x;
    const int lane = tid & 31;
    const int w = tid >> 5;
    const int wm = w & 1;
    const int wncol = w >> 1;

    // load whole B (128x256) fp32 -> fp16 once
    for (int idx = tid; idx < 128 * 32; idx += 256) {
        int row = idx >> 5;
        int colh = (idx & 31) * 8;
        const float4* wp = (const float4*)&W[(size_t)row * HC + colh];
        float4 v0 = wp[0], v1 = wp[1];
        float f[8] = {v0.x, v0.y, v0.z, v0.w, v1.x, v1.y, v1.z, v1.w};
        __half h[8];
#pragma unroll
        for (int q = 0; q < 8; q++) h[q] = __float2half_rn(f[q]);
        *(uint4*)&Bs[row * PADB2 + colh] = *(uint4*)h;
    }

    const int lrow = lane & 7;
    const int lhalf = (lane & 8) ? 8 : 0;
    const int lq = (lane & 16) ? 8 : 0;
    const int gid = lane >> 2, tig = lane & 3;

    float aS[8][2], aD[8][2];
#pragma unroll
    for (int j = 0; j < 8; j++) {
        int col = wncol * 64 + j * 8 + tig * 2;
        aS[j][0] = att_s[col];     aS[j][1] = att_s[col + 1];
        aD[j][0] = att_d[col];     aD[j][1] = att_d[col + 1];
    }

    // preload first chunk
    if (blockIdx.x < NCHUNK) load_a_chunk(x, Abuf[0], blockIdx.x * 64, tid);
    __syncthreads();

    int buf = 0;
    for (int c = blockIdx.x; c < NCHUNK; c += GEMM_GRID, buf ^= 1) {
        const int bm = c * 64;
        if (c + GEMM_GRID < NCHUNK)
            load_a_chunk(x, Abuf[buf ^ 1], (c + GEMM_GRID) * 64, tid);

        const __half* Ah = Abuf[buf];
        float cacc[2][8][4];
#pragma unroll
        for (int i = 0; i < 2; i++)
#pragma unroll
            for (int j = 0; j < 8; j++)
#pragma unroll
                for (int q = 0; q < 4; q++) cacc[i][j][q] = 0.f;

#pragma unroll
        for (int ksi = 0; ksi < 8; ksi++) {
            const int ks = ksi * 16;
            uint32_t bf[8][2];
#pragma unroll
            for (int jj = 0; jj < 4; jj++) {
                int brow = ks + lrow + lhalf;
                int bcol = wncol * 64 + jj * 16 + lq;
                ldsm4t(bf[2 * jj][0], bf[2 * jj][1], bf[2 * jj + 1][0], bf[2 * jj + 1][1],
                       &Bs[brow * PADB2 + bcol]);
            }
#pragma unroll
            for (int i = 0; i < 2; i++) {
                uint32_t af[4];
                int arow = wm * 32 + i * 16 + lrow + lhalf;
                ldsm4(af[0], af[1], af[2], af[3], &Ah[arow * PADA2 + ks + lq]);
#pragma unroll
                for (int j = 0; j < 8; j++) mma16816(cacc[i][j], af, bf[j]);
            }
        }

        // epilogue: store h fp16 + fused dots
#pragma unroll
        for (int i = 0; i < 2; i++) {
            int r0 = bm + wm * 32 + i * 16 + gid;
            int r1 = r0 + 8;
            int h2i = wncol * 32 + tig;
            if (r0 < NN) {
#pragma unroll
                for (int j = 0; j < 8; j++)
                    g_hh[(size_t)r0 * 128 + h2i + j * 4] =
                        __floats2half2_rn(cacc[i][j][0], cacc[i][j][1]);
            }
            if (r1 < NN) {
#pragma unroll
                for (int j = 0; j < 8; j++)
                    g_hh[(size_t)r1 * 128 + h2i + j * 4] =
                        __floats2half2_rn(cacc[i][j][2], cacc[i][j][3]);
            }
            float s0 = 0.f, s1 = 0.f, d0 = 0.f, d1 = 0.f;
#pragma unroll
            for (int j = 0; j < 8; j++) {
                s0 += cacc[i][j][0] * aS[j][0] + cacc[i][j][1] * aS[j][1];
                s1 += cacc[i][j][2] * aS[j][0] + cacc[i][j][3] * aS[j][1];
                d0 += cacc[i][j][0] * aD[j][0] + cacc[i][j][1] * aD[j][1];
                d1 += cacc[i][j][2] * aD[j][0] + cacc[i][j][3] * aD[j][1];
            }
#pragma unroll
            for (int o = 1; o <= 2; o <<= 1) {
                s0 += __shfl_xor_sync(0xFFFFFFFFu, s0, o);
                s1 += __shfl_xor_sync(0xFFFFFFFFu, s1, o);
                d0 += __shfl_xor_sync(0xFFFFFFFFu, d0, o);
                d1 += __shfl_xor_sync(0xFFFFFFFFu, d1, o);
            }
            if (tig == 0) {
                if (r0 < NN) { g_as[r0 * 4 + wncol] = s0; g_ad[r0 * 4 + wncol] = d0; }
                if (r1 < NN) { g_as[r1 * 4 + wncol] = s1; g_ad[r1 * 4 + wncol] = d1; }
            }
        }
        __syncthreads();
    }
}

__device__ __forceinline__ float leaky(float x) { return x > 0.f ? x : 0.2f * x; }

// ---------------- layer-1 softmax+aggregation fused with layer-2 projection ----------------
// R9 form: one warp per node, grid-sized launch (dynamic CTA load balancing).
__device__ __forceinline__ void agg_edge1(float asv, uint4 r, float advh,
                                          float* a, float& den) {
    float w = __expf(leaky(asv + advh));
    den += w;
    float2 f0 = __half22float2(*(__half2*)&r.x);
    float2 f1 = __half22float2(*(__half2*)&r.y);
    float2 f2 = __half22float2(*(__half2*)&r.z);
    float2 f3 = __half22float2(*(__half2*)&r.w);
    a[0] += w * f0.x; a[1] += w * f0.y;
    a[2] += w * f1.x; a[3] += w * f1.y;
    a[4] += w * f2.x; a[5] += w * f2.y;
    a[6] += w * f3.x; a[7] += w * f3.y;
}

__global__ void k_agg1(const float* __restrict__ bias,
                       const float* __restrict__ W2) {
    int gw = (blockIdx.x * blockDim.x + threadIdx.x) >> 5;
    if (gw >= NN) return;
    int lane = threadIdx.x & 31;
    int head = lane >> 3;
    int beg = g_off[gw];
    int end = beg + g_deg[gw];
    float advh = g_ad[gw * 4 + head];

    float a[8];
#pragma unroll
    for (int j = 0; j < 8; j++) a[j] = 0.f;
    float den = 0.f;

    int p = beg;
    for (; p + 4 <= end; p += 4) {
        int s0 = g_csrc[p], s1 = g_csrc[p + 1], s2 = g_csrc[p + 2], s3 = g_csrc[p + 3];
        float as0 = g_as[s0 * 4 + head];
        float as1 = g_as[s1 * 4 + head];
        float as2 = g_as[s2 * 4 + head];
        float as3 = g_as[s3 * 4 + head];
        uint4 r0 = *(const uint4*)(g_hh + (size_t)s0 * 128 + lane * 4);
        uint4 r1 = *(const uint4*)(g_hh + (size_t)s1 * 128 + lane * 4);
        uint4 r2 = *(const uint4*)(g_hh + (size_t)s2 * 128 + lane * 4);
        uint4 r3 = *(const uint4*)(g_hh + (size_t)s3 * 128 + lane * 4);
        agg_edge1(as0, r0, advh, a, den);
        agg_edge1(as1, r1, advh, a, den);
        agg_edge1(as2, r2, advh, a, den);
        agg_edge1(as3, r3, advh, a, den);
    }
    for (; p < end; p++) {
        int s = g_csrc[p];
        float asv = g_as[s * 4 + head];
        uint4 r = *(const uint4*)(g_hh + (size_t)s * 128 + lane * 4);
        agg_edge1(asv, r, advh, a, den);
    }

    float inv = 1.f / den;
    int colb = lane * 8;
    const float4* bv = (const float4*)(bias + colb);
    float4 b0 = bv[0], b1 = bv[1];
    const float4* wv = (const float4*)(W2 + colb);
    float4 w0 = wv[0], w1 = wv[1];
    float pr = 0.f, t;
    t = a[0] * inv + b0.x; t = t > 0.f ? t : expm1f(t); pr += t * w0.x;
    t = a[1] * inv + b0.y; t = t > 0.f ? t : expm1f(t); pr += t * w0.y;
    t = a[2] * inv + b0.z; t = t > 0.f ? t : expm1f(t); pr += t * w0.z;
    t = a[3] * inv + b0.w; t = t > 0.f ? t : expm1f(t); pr += t * w0.w;
    t = a[4] * inv + b1.x; t = t > 0.f ? t : expm1f(t); pr += t * w1.x;
    t = a[5] * inv + b1.y; t = t > 0.f ? t : expm1f(t); pr += t * w1.y;
    t = a[6] * inv + b1.z; t = t > 0.f ? t : expm1f(t); pr += t * w1.z;
    t = a[7] * inv + b1.w; t = t > 0.f ? t : expm1f(t); pr += t * w1.w;
#pragma unroll
    for (int o = 16; o; o >>= 1) pr += __shfl_xor_sync(0xFFFFFFFFu, pr, o);
    if (lane == 0) g_z[gw] = pr;
}

// ---------------- layer-2 softmax + aggregation ----------------
__global__ void k_agg2(const float* __restrict__ att_s2,
                       const float* __restrict__ att_d2,
                       const float* __restrict__ bias2,
                       float* __restrict__ out) {
    int gw = (blockIdx.x * blockDim.x + threadIdx.x) >> 5;
    if (gw >= NN) return;
    int lane = threadIdx.x & 31;
    float atts = att_s2[0], attd = att_d2[0];
    int beg = g_off[gw];
    int end = beg + g_deg[gw];
    float adv = g_z[gw] * attd;

    float den = 0.f, acc = 0.f;
    for (int p = beg + lane; p < end; p += 32) {
        int s = g_csrc[p];
        float zs = g_z[s];
        float w = __expf(leaky(zs * atts + adv));
        den += w;
        acc += w * zs;
    }
#pragma unroll
    for (int o = 16; o; o >>= 1) {
        den += __shfl_xor_sync(0xFFFFFFFFu, den, o);
        acc += __shfl_xor_sync(0xFFFFFFFFu, acc, o);
    }
    if (lane == 0) out[gw] = acc / den + bias2[0];
}

// ---------------- launch ----------------
extern "C" void kernel_launch(void* const* d_in, const int* in_sizes, int n_in,
                              void* d_out, int out_size) {
    const float* x     = (const float*)d_in[0];
    const int*   ei    = (const int*)d_in[1];
    const float* W1    = (const float*)d_in[2];
    const float* atts1 = (const float*)d_in[3];
    const float* attd1 = (const float*)d_in[4];
    const float* bias1 = (const float*)d_in[5];
    const float* W2    = (const float*)d_in[6];
    const float* atts2 = (const float*)d_in[7];
    const float* attd2 = (const float*)d_in[8];
    const float* bias2 = (const float*)d_in[9];
    float* out = (float*)d_out;
    (void)in_sizes; (void)n_in; (void)out_size;

    cudaFuncSetAttribute(k_gemm_mma, cudaFuncAttributeMaxDynamicSharedMemorySize,
                         SMEM_TOTAL_GEMM);

    // fork: CSR chain on g_s2, GEMM on main stream
    cudaEventRecord(g_evFork, 0);
    cudaStreamWaitEvent(g_s2, g_evFork, 0);

    cudaMemsetAsync(g_deg_addr, 0, NN * sizeof(int), g_s2);
    cudaMemsetAsync(g_total_addr, 0, sizeof(int), g_s2);
    k_count<<<(EE / 4 + 255) / 256, 256, 0, g_s2>>>((const int4*)(ei + EE));
    k_offsets<<<(NN + 255) / 256, 256, 0, g_s2>>>();
    k_scatter<<<(EE / 4 + NN + 255) / 256, 256, 0, g_s2>>>(ei);
    cudaEventRecord(g_evJoin, g_s2);

    k_gemm_mma<<<GEMM_GRID, 256, SMEM_TOTAL_GEMM>>>(x, W1, atts1, attd1);

    cudaStreamWaitEvent(0, g_evJoin, 0);

    int warp_blocks = (NN * 32 + 255) / 256;
    k_agg1<<<warp_blocks, 256>>>(bias1, W2);
    k_agg2<<<warp_blocks, 256>>>(atts2, attd2, bias2, out);
}

// round 13
// speedup vs baseline: 1.1407x; 1.0334x over previous
#include <cuda_runtime.h>
#include <cuda_fp16.h>
#include <cstdint>

#define NN    50000
#define EE    800000
#define INCH  128
#define HC    256             // 4 heads * 64
#define CAP   96              // per-node bucket capacity (Poisson(17): P(deg>=96) ~ 1e-35)

// ---------------- static scratch ----------------
__device__ __align__(16) __half2 g_hh[(size_t)NN * (HC / 2)]; // layer-1 features fp16
__device__ float g_as[NN * 4];
__device__ float g_ad[NN * 4];
__device__ float g_z[NN];
__device__ int   g_deg[NN];                                   // bucket fill counters
__device__ int   g_csrc[(size_t)NN * CAP];                    // bucketed CSR-by-dst

// ---------------- GEMM tiling ----------------
#define GEMM_GRID 296            // 2 CTAs/SM, fully resident persistent grid
#define NCHUNK 782               // ceil(NN/64)
#define PADB2 264                // B row pitch (halves)
#define PADA2 136                // A row pitch (halves)
#define SMEM_B_BYTES (128 * PADB2 * 2)             // 67584
#define SMEM_A_BYTES (64 * PADA2 * 2)              // 17408 per buffer
#define SMEM_TOTAL_GEMM (SMEM_B_BYTES + 2 * SMEM_A_BYTES)   // 102400

__global__ void k_gemm_mma(const float*, const float*, const float*, const float*);

// ---------------- streams/events + symbol addresses ----------------
static cudaStream_t g_s2;
static cudaEvent_t g_evFork, g_evJoin;
static void* g_deg_addr;
namespace {
struct SInit {
    SInit() {
        cudaStreamCreateWithFlags(&g_s2, cudaStreamNonBlocking);
        cudaEventCreateWithFlags(&g_evFork, cudaEventDisableTiming);
        cudaEventCreateWithFlags(&g_evJoin, cudaEventDisableTiming);
        cudaGetSymbolAddress(&g_deg_addr, g_deg);
        cudaFuncSetAttribute(k_gemm_mma, cudaFuncAttributeMaxDynamicSharedMemorySize,
                             SMEM_TOTAL_GEMM);
    }
};
SInit sinit_;
}

// ---------------- single-pass bucketed CSR build ----------------
__global__ void k_scatter(const int* __restrict__ ei) {
    int e4 = blockIdx.x * blockDim.x + threadIdx.x;
    int nvec = EE / 4;
    if (e4 < nvec) {
        int4 s = ((const int4*)ei)[e4];
        int4 d = ((const int4*)(ei + EE))[e4];
        g_csrc[(size_t)d.x * CAP + atomicAdd(&g_deg[d.x], 1)] = s.x;
        g_csrc[(size_t)d.y * CAP + atomicAdd(&g_deg[d.y], 1)] = s.y;
        g_csrc[(size_t)d.z * CAP + atomicAdd(&g_deg[d.z], 1)] = s.z;
        g_csrc[(size_t)d.w * CAP + atomicAdd(&g_deg[d.w], 1)] = s.w;
    } else {
        int n = e4 - nvec;   // self loops
        if (n < NN) g_csrc[(size_t)n * CAP + atomicAdd(&g_deg[n], 1)] = n;
    }
}

// ---------------- tensor-core GEMM: persistent, B resident, A double-buffered ----------------
__device__ __forceinline__ void ldsm4(uint32_t& r0, uint32_t& r1, uint32_t& r2, uint32_t& r3,
                                      const __half* p) {
    uint32_t a = (uint32_t)__cvta_generic_to_shared(p);
    asm volatile("ldmatrix.sync.aligned.m8n8.x4.shared.b16 {%0,%1,%2,%3},[%4];"
                 : "=r"(r0), "=r"(r1), "=r"(r2), "=r"(r3) : "r"(a));
}
__device__ __forceinline__ void ldsm4t(uint32_t& r0, uint32_t& r1, uint32_t& r2, uint32_t& r3,
                                       const __half* p) {
    uint32_t a = (uint32_t)__cvta_generic_to_shared(p);
    asm volatile("ldmatrix.sync.aligned.m8n8.x4.trans.shared.b16 {%0,%1,%2,%3},[%4];"
                 : "=r"(r0), "=r"(r1), "=r"(r2), "=r"(r3) : "r"(a));
}
__device__ __forceinline__ void mma16816(float* c, const uint32_t* a, const uint32_t* b) {
    asm volatile(
        "mma.sync.aligned.m16n8k16.row.col.f32.f16.f16.f32 "
        "{%0,%1,%2,%3},{%4,%5,%6,%7},{%8,%9},{%0,%1,%2,%3};"
        : "+f"(c[0]), "+f"(c[1]), "+f"(c[2]), "+f"(c[3])
        : "r"(a[0]), "r"(a[1]), "r"(a[2]), "r"(a[3]), "r"(b[0]), "r"(b[1]));
}

__device__ __forceinline__ void load_a_chunk(const float* __restrict__ x,
                                             __half* __restrict__ Adst, int bm, int tid) {
    for (int idx = tid; idx < 64 * 16; idx += 256) {
        int row = idx >> 4;
        int colh = (idx & 15) * 8;
        int grow = bm + row; if (grow >= NN) grow = NN - 1;
        const float4* xp = (const float4*)&x[(size_t)grow * INCH + colh];
        float4 v0 = xp[0], v1 = xp[1];
        float f[8] = {v0.x, v0.y, v0.z, v0.w, v1.x, v1.y, v1.z, v1.w};
        __half h[8];
#pragma unroll
        for (int q = 0; q < 8; q++) h[q] = __float2half_rn(f[q]);
        *(uint4*)&Adst[row * PADA2 + colh] = *(uint4*)h;
    }
}

__global__ __launch_bounds__(256, 2) void k_gemm_mma(const float* __restrict__ x,
                                                     const float* __restrict__ W,
                                                     const float* __restrict__ att_s,
                                                     const float* __restrict__ att_d) {
    extern __shared__ char smem[];
    __half* Bs = (__half*)smem;                               // [128][PADB2]
    __half* Abuf[2] = {(__half*)(smem + SMEM_B_BYTES),
                       (__half*)(smem + SMEM_B_BYTES + SMEM_A_BYTES)};
    const int tid = threadIdx.x;
    const int lane = tid & 31;
    const int w = tid >> 5;
    const int wm = w & 1;
    const int wncol = w >> 1;

    // load whole B (128x256) fp32 -> fp16 once
    for (int idx = tid; idx < 128 * 32; idx += 256) {
        int row = idx >> 5;
        int colh = (idx & 31) * 8;
        const float4* wp = (const float4*)&W[(size_t)row * HC + colh];
        float4 v0 = wp[0], v1 = wp[1];
        float f[8] = {v0.x, v0.y, v0.z, v0.w, v1.x, v1.y, v1.z, v1.w};
        __half h[8];
#pragma unroll
        for (int q = 0; q < 8; q++) h[q] = __float2half_rn(f[q]);
        *(uint4*)&Bs[row * PADB2 + colh] = *(uint4*)h;
    }

    const int lrow = lane & 7;
    const int lhalf = (lane & 8) ? 8 : 0;
    const int lq = (lane & 16) ? 8 : 0;
    const int gid = lane >> 2, tig = lane & 3;

    float aS[8][2], aD[8][2];
#pragma unroll
    for (int j = 0; j < 8; j++) {
        int col = wncol * 64 + j * 8 + tig * 2;
        aS[j][0] = att_s[col];     aS[j][1] = att_s[col + 1];
        aD[j][0] = att_d[col];     aD[j][1] = att_d[col + 1];
    }

    if (blockIdx.x < NCHUNK) load_a_chunk(x, Abuf[0], blockIdx.x * 64, tid);
    __syncthreads();

    int buf = 0;
    for (int c = blockIdx.x; c < NCHUNK; c += GEMM_GRID, buf ^= 1) {
        const int bm = c * 64;
        if (c + GEMM_GRID < NCHUNK)
            load_a_chunk(x, Abuf[buf ^ 1], (c + GEMM_GRID) * 64, tid);

        const __half* Ah = Abuf[buf];
        float cacc[2][8][4];
#pragma unroll
        for (int i = 0; i < 2; i++)
#pragma unroll
            for (int j = 0; j < 8; j++)
#pragma unroll
                for (int q = 0; q < 4; q++) cacc[i][j][q] = 0.f;

#pragma unroll
        for (int ksi = 0; ksi < 8; ksi++) {
            const int ks = ksi * 16;
            uint32_t bf[8][2];
#pragma unroll
            for (int jj = 0; jj < 4; jj++) {
                int brow = ks + lrow + lhalf;
                int bcol = wncol * 64 + jj * 16 + lq;
                ldsm4t(bf[2 * jj][0], bf[2 * jj][1], bf[2 * jj + 1][0], bf[2 * jj + 1][1],
                       &Bs[brow * PADB2 + bcol]);
            }
#pragma unroll
            for (int i = 0; i < 2; i++) {
                uint32_t af[4];
                int arow = wm * 32 + i * 16 + lrow + lhalf;
                ldsm4(af[0], af[1], af[2], af[3], &Ah[arow * PADA2 + ks + lq]);
#pragma unroll
                for (int j = 0; j < 8; j++) mma16816(cacc[i][j], af, bf[j]);
            }
        }

        // epilogue: store h fp16 + fused dots
#pragma unroll
        for (int i = 0; i < 2; i++) {
            int r0 = bm + wm * 32 + i * 16 + gid;
            int r1 = r0 + 8;
            int h2i = wncol * 32 + tig;
            if (r0 < NN) {
#pragma unroll
                for (int j = 0; j < 8; j++)
                    g_hh[(size_t)r0 * 128 + h2i + j * 4] =
                        __floats2half2_rn(cacc[i][j][0], cacc[i][j][1]);
            }
            if (r1 < NN) {
#pragma unroll
                for (int j = 0; j < 8; j++)
                    g_hh[(size_t)r1 * 128 + h2i + j * 4] =
                        __floats2half2_rn(cacc[i][j][2], cacc[i][j][3]);
            }
            float s0 = 0.f, s1 = 0.f, d0 = 0.f, d1 = 0.f;
#pragma unroll
            for (int j = 0; j < 8; j++) {
                s0 += cacc[i][j][0] * aS[j][0] + cacc[i][j][1] * aS[j][1];
                s1 += cacc[i][j][2] * aS[j][0] + cacc[i][j][3] * aS[j][1];
                d0 += cacc[i][j][0] * aD[j][0] + cacc[i][j][1] * aD[j][1];
                d1 += cacc[i][j][2] * aD[j][0] + cacc[i][j][3] * aD[j][1];
            }
#pragma unroll
            for (int o = 1; o <= 2; o <<= 1) {
                s0 += __shfl_xor_sync(0xFFFFFFFFu, s0, o);
                s1 += __shfl_xor_sync(0xFFFFFFFFu, s1, o);
                d0 += __shfl_xor_sync(0xFFFFFFFFu, d0, o);
                d1 += __shfl_xor_sync(0xFFFFFFFFu, d1, o);
            }
            if (tig == 0) {
                if (r0 < NN) { g_as[r0 * 4 + wncol] = s0; g_ad[r0 * 4 + wncol] = d0; }
                if (r1 < NN) { g_as[r1 * 4 + wncol] = s1; g_ad[r1 * 4 + wncol] = d1; }
            }
        }
        __syncthreads();
    }
}

__device__ __forceinline__ float leaky(float x) { return x > 0.f ? x : 0.2f * x; }

// ---------------- layer-1 softmax+aggregation fused with layer-2 projection ----------------
__device__ __forceinline__ void agg_edge1(float asv, uint4 r, float advh,
                                          float* a, float& den) {
    float w = __expf(leaky(asv + advh));
    den += w;
    float2 f0 = __half22float2(*(__half2*)&r.x);
    float2 f1 = __half22float2(*(__half2*)&r.y);
    float2 f2 = __half22float2(*(__half2*)&r.z);
    float2 f3 = __half22float2(*(__half2*)&r.w);
    a[0] += w * f0.x; a[1] += w * f0.y;
    a[2] += w * f1.x; a[3] += w * f1.y;
    a[4] += w * f2.x; a[5] += w * f2.y;
    a[6] += w * f3.x; a[7] += w * f3.y;
}

__global__ void k_agg1(const float* __restrict__ bias,
                       const float* __restrict__ W2) {
    int gw = (blockIdx.x * blockDim.x + threadIdx.x) >> 5;
    if (gw >= NN) return;
    int lane = threadIdx.x & 31;
    int head = lane >> 3;
    int beg = gw * CAP;
    int end = beg + g_deg[gw];
    float advh = g_ad[gw * 4 + head];

    float a[8];
#pragma unroll
    for (int j = 0; j < 8; j++) a[j] = 0.f;
    float den = 0.f;

    int p = beg;
    for (; p + 4 <= end; p += 4) {
        int s0 = g_csrc[p], s1 = g_csrc[p + 1], s2 = g_csrc[p + 2], s3 = g_csrc[p + 3];
        float as0 = g_as[s0 * 4 + head];
        float as1 = g_as[s1 * 4 + head];
        float as2 = g_as[s2 * 4 + head];
        float as3 = g_as[s3 * 4 + head];
        uint4 r0 = *(const uint4*)(g_hh + (size_t)s0 * 128 + lane * 4);
        uint4 r1 = *(const uint4*)(g_hh + (size_t)s1 * 128 + lane * 4);
        uint4 r2 = *(const uint4*)(g_hh + (size_t)s2 * 128 + lane * 4);
        uint4 r3 = *(const uint4*)(g_hh + (size_t)s3 * 128 + lane * 4);
        agg_edge1(as0, r0, advh, a, den);
        agg_edge1(as1, r1, advh, a, den);
        agg_edge1(as2, r2, advh, a, den);
        agg_edge1(as3, r3, advh, a, den);
    }
    for (; p < end; p++) {
        int s = g_csrc[p];
        float asv = g_as[s * 4 + head];
        uint4 r = *(const uint4*)(g_hh + (size_t)s * 128 + lane * 4);
        agg_edge1(asv, r, advh, a, den);
    }

    float inv = 1.f / den;
    int colb = lane * 8;
    const float4* bv = (const float4*)(bias + colb);
    float4 b0 = bv[0], b1 = bv[1];
    const float4* wv = (const float4*)(W2 + colb);
    float4 w0 = wv[0], w1 = wv[1];
    float pr = 0.f, t;
    t = a[0] * inv + b0.x; t = t > 0.f ? t : expm1f(t); pr += t * w0.x;
    t = a[1] * inv + b0.y; t = t > 0.f ? t : expm1f(t); pr += t * w0.y;
    t = a[2] * inv + b0.z; t = t > 0.f ? t : expm1f(t); pr += t * w0.z;
    t = a[3] * inv + b0.w; t = t > 0.f ? t : expm1f(t); pr += t * w0.w;
    t = a[4] * inv + b1.x; t = t > 0.f ? t : expm1f(t); pr += t * w1.x;
    t = a[5] * inv + b1.y; t = t > 0.f ? t : expm1f(t); pr += t * w1.y;
    t = a[6] * inv + b1.z; t = t > 0.f ? t : expm1f(t); pr += t * w1.z;
    t = a[7] * inv + b1.w; t = t > 0.f ? t : expm1f(t); pr += t * w1.w;
#pragma unroll
    for (int o = 16; o; o >>= 1) pr += __shfl_xor_sync(0xFFFFFFFFu, pr, o);
    if (lane == 0) g_z[gw] = pr;
}

// ---------------- layer-2 softmax + aggregation ----------------
__global__ void k_agg2(const float* __restrict__ att_s2,
                       const float* __restrict__ att_d2,
                       const float* __restrict__ bias2,
                       float* __restrict__ out) {
    int gw = (blockIdx.x * blockDim.x + threadIdx.x) >> 5;
    if (gw >= NN) return;
    int lane = threadIdx.x & 31;
    float atts = att_s2[0], attd = att_d2[0];
    int beg = gw * CAP;
    int end = beg + g_deg[gw];
    float adv = g_z[gw] * attd;

    float den = 0.f, acc = 0.f;
    for (int p = beg + lane; p < end; p += 32) {
        int s = g_csrc[p];
        float zs = g_z[s];
        float w = __expf(leaky(zs * atts + adv));
        den += w;
        acc += w * zs;
    }
#pragma unroll
    for (int o = 16; o; o >>= 1) {
        den += __shfl_xor_sync(0xFFFFFFFFu, den, o);
        acc += __shfl_xor_sync(0xFFFFFFFFu, acc, o);
    }
    if (lane == 0) out[gw] = acc / den + bias2[0];
}

// ---------------- launch ----------------
extern "C" void kernel_launch(void* const* d_in, const int* in_sizes, int n_in,
                              void* d_out, int out_size) {
    const float* x     = (const float*)d_in[0];
    const int*   ei    = (const int*)d_in[1];
    const float* W1    = (const float*)d_in[2];
    const float* atts1 = (const float*)d_in[3];
    const float* attd1 = (const float*)d_in[4];
    const float* bias1 = (const float*)d_in[5];
    const float* W2    = (const float*)d_in[6];
    const float* atts2 = (const float*)d_in[7];
    const float* attd2 = (const float*)d_in[8];
    const float* bias2 = (const float*)d_in[9];
    float* out = (float*)d_out;
    (void)in_sizes; (void)n_in; (void)out_size;

    cudaFuncSetAttribute(k_gemm_mma, cudaFuncAttributeMaxDynamicSharedMemorySize,
                         SMEM_TOTAL_GEMM);

    // fork: single-pass bucket scatter on g_s2 (launched FIRST so its short
    // blocks drain ahead of the RF-saturating persistent gemm), gemm on main
    cudaEventRecord(g_evFork, 0);
    cudaStreamWaitEvent(g_s2, g_evFork, 0);

    cudaMemsetAsync(g_deg_addr, 0, NN * sizeof(int), g_s2);
    k_scatter<<<(EE / 4 + NN + 255) / 256, 256, 0, g_s2>>>(ei);
    cudaEventRecord(g_evJoin, g_s2);

    k_gemm_mma<<<GEMM_GRID, 256, SMEM_TOTAL_GEMM>>>(x, W1, atts1, attd1);

    cudaStreamWaitEvent(0, g_evJoin, 0);

    int warp_blocks = (NN * 32 + 255) / 256;
    k_agg1<<<warp_blocks, 256>>>(bias1, W2);
    k_agg2<<<warp_blocks, 256>>>(atts2, attd2, bias2, out);
}

// round 14
// speedup vs baseline: 1.1683x; 1.0242x over previous
#include <cuda_runtime.h>
#include <cuda_fp16.h>
#include <cstdint>

#define NN    50000
#define EE    800000
#define INCH  128
#define HC    256             // 4 heads * 64
#define CAP   96              // per-node bucket capacity (Poisson(17): P(deg>=96) ~ 1e-35)

// ---------------- static scratch ----------------
__device__ __align__(16) __half2 g_hh[(size_t)NN * (HC / 2)]; // layer-1 features fp16
__device__ float g_as[NN * 4];
__device__ float g_ad[NN * 4];
__device__ float g_z[NN];
__device__ int   g_deg[NN];                                   // bucket fill counters
__device__ int   g_csrc[(size_t)NN * CAP];                    // bucketed CSR-by-dst

// ---------------- GEMM tiling ----------------
#define GEMM_GRID 296            // 2 CTAs/SM, fully resident persistent grid
#define NCHUNK 782               // ceil(NN/64)
#define PADB2 264                // B row pitch (halves)
#define PADA2 136                // A row pitch (halves)
#define SMEM_B_BYTES (128 * PADB2 * 2)             // 67584
#define SMEM_A_BYTES (64 * PADA2 * 2)              // 17408 per buffer
#define SMEM_TOTAL_GEMM (SMEM_B_BYTES + 2 * SMEM_A_BYTES)   // 102400

__global__ void k_gemm_mma(const float*, const int*, const float*, const float*, const float*);

// ---------------- symbol addresses (static init; no allocs in launch) ----------------
static void* g_deg_addr;
namespace {
struct SInit {
    SInit() {
        cudaGetSymbolAddress(&g_deg_addr, g_deg);
        cudaFuncSetAttribute(k_gemm_mma, cudaFuncAttributeMaxDynamicSharedMemorySize,
                             SMEM_TOTAL_GEMM);
    }
};
SInit sinit_;
}

// ---------------- tensor-core GEMM + fused edge scatter ----------------
__device__ __forceinline__ void ldsm4(uint32_t& r0, uint32_t& r1, uint32_t& r2, uint32_t& r3,
                                      const __half* p) {
    uint32_t a = (uint32_t)__cvta_generic_to_shared(p);
    asm volatile("ldmatrix.sync.aligned.m8n8.x4.shared.b16 {%0,%1,%2,%3},[%4];"
                 : "=r"(r0), "=r"(r1), "=r"(r2), "=r"(r3) : "r"(a));
}
__device__ __forceinline__ void ldsm4t(uint32_t& r0, uint32_t& r1, uint32_t& r2, uint32_t& r3,
                                       const __half* p) {
    uint32_t a = (uint32_t)__cvta_generic_to_shared(p);
    asm volatile("ldmatrix.sync.aligned.m8n8.x4.trans.shared.b16 {%0,%1,%2,%3},[%4];"
                 : "=r"(r0), "=r"(r1), "=r"(r2), "=r"(r3) : "r"(a));
}
__device__ __forceinline__ void mma16816(float* c, const uint32_t* a, const uint32_t* b) {
    asm volatile(
        "mma.sync.aligned.m16n8k16.row.col.f32.f16.f16.f32 "
        "{%0,%1,%2,%3},{%4,%5,%6,%7},{%8,%9},{%0,%1,%2,%3};"
        : "+f"(c[0]), "+f"(c[1]), "+f"(c[2]), "+f"(c[3])
        : "r"(a[0]), "r"(a[1]), "r"(a[2]), "r"(a[3]), "r"(b[0]), "r"(b[1]));
}

__device__ __forceinline__ void load_a_chunk(const float* __restrict__ x,
                                             __half* __restrict__ Adst, int bm, int tid) {
    for (int idx = tid; idx < 64 * 16; idx += 256) {
        int row = idx >> 4;
        int colh = (idx & 15) * 8;
        int grow = bm + row; if (grow >= NN) grow = NN - 1;
        const float4* xp = (const float4*)&x[(size_t)grow * INCH + colh];
        float4 v0 = xp[0], v1 = xp[1];
        float f[8] = {v0.x, v0.y, v0.z, v0.w, v1.x, v1.y, v1.z, v1.w};
        __half h[8];
#pragma unroll
        for (int q = 0; q < 8; q++) h[q] = __float2half_rn(f[q]);
        *(uint4*)&Adst[row * PADA2 + colh] = *(uint4*)h;
    }
}

__global__ __launch_bounds__(256, 2) void k_gemm_mma(const float* __restrict__ x,
                                                     const int* __restrict__ ei,
                                                     const float* __restrict__ W,
                                                     const float* __restrict__ att_s,
                                                     const float* __restrict__ att_d) {
    extern __shared__ char smem[];
    __half* Bs = (__half*)smem;                               // [128][PADB2]
    __half* Abuf[2] = {(__half*)(smem + SMEM_B_BYTES),
                       (__half*)(smem + SMEM_B_BYTES + SMEM_A_BYTES)};
    const int tid = threadIdx.x;
    const int lane = tid & 31;
    const int w = tid >> 5;
    const int wm = w & 1;
    const int wncol = w >> 1;

    // ---- phase 0: edge scatter (grid-strided share; interleaves with gemm work
    //      across blocks; no intra-kernel consumer of g_csrc/g_deg) ----
    {
        const int nvec = EE / 4;
        const int items = nvec + NN;
        for (int it = blockIdx.x * 256 + tid; it < items; it += GEMM_GRID * 256) {
            if (it < nvec) {
                int4 s = ((const int4*)ei)[it];
                int4 d = ((const int4*)(ei + EE))[it];
                g_csrc[(size_t)d.x * CAP + atomicAdd(&g_deg[d.x], 1)] = s.x;
                g_csrc[(size_t)d.y * CAP + atomicAdd(&g_deg[d.y], 1)] = s.y;
                g_csrc[(size_t)d.z * CAP + atomicAdd(&g_deg[d.z], 1)] = s.z;
                g_csrc[(size_t)d.w * CAP + atomicAdd(&g_deg[d.w], 1)] = s.w;
            } else {
                int n = it - nvec;   // self loop
                g_csrc[(size_t)n * CAP + atomicAdd(&g_deg[n], 1)] = n;
            }
        }
    }

    // ---- load whole B (128x256) fp32 -> fp16 once ----
    for (int idx = tid; idx < 128 * 32; idx += 256) {
        int row = idx >> 5;
        int colh = (idx & 31) * 8;
        const float4* wp = (const float4*)&W[(size_t)row * HC + colh];
        float4 v0 = wp[0], v1 = wp[1];
        float f[8] = {v0.x, v0.y, v0.z, v0.w, v1.x, v1.y, v1.z, v1.w};
        __half h[8];
#pragma unroll
        for (int q = 0; q < 8; q++) h[q] = __float2half_rn(f[q]);
        *(uint4*)&Bs[row * PADB2 + colh] = *(uint4*)h;
    }

    const int lrow = lane & 7;
    const int lhalf = (lane & 8) ? 8 : 0;
    const int lq = (lane & 16) ? 8 : 0;
    const int gid = lane >> 2, tig = lane & 3;

    float aS[8][2], aD[8][2];
#pragma unroll
    for (int j = 0; j < 8; j++) {
        int col = wncol * 64 + j * 8 + tig * 2;
        aS[j][0] = att_s[col];     aS[j][1] = att_s[col + 1];
        aD[j][0] = att_d[col];     aD[j][1] = att_d[col + 1];
    }

    if (blockIdx.x < NCHUNK) load_a_chunk(x, Abuf[0], blockIdx.x * 64, tid);
    __syncthreads();

    int buf = 0;
    for (int c = blockIdx.x; c < NCHUNK; c += GEMM_GRID, buf ^= 1) {
        const int bm = c * 64;
        if (c + GEMM_GRID < NCHUNK)
            load_a_chunk(x, Abuf[buf ^ 1], (c + GEMM_GRID) * 64, tid);

        const __half* Ah = Abuf[buf];
        float cacc[2][8][4];
#pragma unroll
        for (int i = 0; i < 2; i++)
#pragma unroll
            for (int j = 0; j < 8; j++)
#pragma unroll
                for (int q = 0; q < 4; q++) cacc[i][j][q] = 0.f;

#pragma unroll
        for (int ksi = 0; ksi < 8; ksi++) {
            const int ks = ksi * 16;
            uint32_t bf[8][2];
#pragma unroll
            for (int jj = 0; jj < 4; jj++) {
                int brow = ks + lrow + lhalf;
                int bcol = wncol * 64 + jj * 16 + lq;
                ldsm4t(bf[2 * jj][0], bf[2 * jj][1], bf[2 * jj + 1][0], bf[2 * jj + 1][1],
                       &Bs[brow * PADB2 + bcol]);
            }
#pragma unroll
            for (int i = 0; i < 2; i++) {
                uint32_t af[4];
                int arow = wm * 32 + i * 16 + lrow + lhalf;
                ldsm4(af[0], af[1], af[2], af[3], &Ah[arow * PADA2 + ks + lq]);
#pragma unroll
                for (int j = 0; j < 8; j++) mma16816(cacc[i][j], af, bf[j]);
            }
        }

        // epilogue: store h fp16 + fused dots
#pragma unroll
        for (int i = 0; i < 2; i++) {
            int r0 = bm + wm * 32 + i * 16 + gid;
            int r1 = r0 + 8;
            int h2i = wncol * 32 + tig;
            if (r0 < NN) {
#pragma unroll
                for (int j = 0; j < 8; j++)
                    g_hh[(size_t)r0 * 128 + h2i + j * 4] =
                        __floats2half2_rn(cacc[i][j][0], cacc[i][j][1]);
            }
            if (r1 < NN) {
#pragma unroll
                for (int j = 0; j < 8; j++)
                    g_hh[(size_t)r1 * 128 + h2i + j * 4] =
                        __floats2half2_rn(cacc[i][j][2], cacc[i][j][3]);
            }
            float s0 = 0.f, s1 = 0.f, d0 = 0.f, d1 = 0.f;
#pragma unroll
            for (int j = 0; j < 8; j++) {
                s0 += cacc[i][j][0] * aS[j][0] + cacc[i][j][1] * aS[j][1];
                s1 += cacc[i][j][2] * aS[j][0] + cacc[i][j][3] * aS[j][1];
                d0 += cacc[i][j][0] * aD[j][0] + cacc[i][j][1] * aD[j][1];
                d1 += cacc[i][j][2] * aD[j][0] + cacc[i][j][3] * aD[j][1];
            }
#pragma unroll
            for (int o = 1; o <= 2; o <<= 1) {
                s0 += __shfl_xor_sync(0xFFFFFFFFu, s0, o);
                s1 += __shfl_xor_sync(0xFFFFFFFFu, s1, o);
                d0 += __shfl_xor_sync(0xFFFFFFFFu, d0, o);
                d1 += __shfl_xor_sync(0xFFFFFFFFu, d1, o);
            }
            if (tig == 0) {
                if (r0 < NN) { g_as[r0 * 4 + wncol] = s0; g_ad[r0 * 4 + wncol] = d0; }
                if (r1 < NN) { g_as[r1 * 4 + wncol] = s1; g_ad[r1 * 4 + wncol] = d1; }
            }
        }
        __syncthreads();
    }
}

__device__ __forceinline__ float leaky(float x) { return x > 0.f ? x : 0.2f * x; }

// ---------------- layer-1 softmax+aggregation fused with layer-2 projection ----------------
__device__ __forceinline__ void agg_edge1(float asv, uint4 r, float advh,
                                          float* a, float& den) {
    float w = __expf(leaky(asv + advh));
    den += w;
    float2 f0 = __half22float2(*(__half2*)&r.x);
    float2 f1 = __half22float2(*(__half2*)&r.y);
    float2 f2 = __half22float2(*(__half2*)&r.z);
    float2 f3 = __half22float2(*(__half2*)&r.w);
    a[0] += w * f0.x; a[1] += w * f0.y;
    a[2] += w * f1.x; a[3] += w * f1.y;
    a[4] += w * f2.x; a[5] += w * f2.y;
    a[6] += w * f3.x; a[7] += w * f3.y;
}

__global__ void k_agg1(const float* __restrict__ bias,
                       const float* __restrict__ W2) {
    int gw = (blockIdx.x * blockDim.x + threadIdx.x) >> 5;
    if (gw >= NN) return;
    int lane = threadIdx.x & 31;
    int head = lane >> 3;
    int beg = gw * CAP;
    int end = beg + g_deg[gw];
    float advh = g_ad[gw * 4 + head];

    float a[8];
#pragma unroll
    for (int j = 0; j < 8; j++) a[j] = 0.f;
    float den = 0.f;

    int p = beg;
    for (; p + 4 <= end; p += 4) {
        int s0 = g_csrc[p], s1 = g_csrc[p + 1], s2 = g_csrc[p + 2], s3 = g_csrc[p + 3];
        float as0 = g_as[s0 * 4 + head];
        float as1 = g_as[s1 * 4 + head];
        float as2 = g_as[s2 * 4 + head];
        float as3 = g_as[s3 * 4 + head];
        uint4 r0 = *(const uint4*)(g_hh + (size_t)s0 * 128 + lane * 4);
        uint4 r1 = *(const uint4*)(g_hh + (size_t)s1 * 128 + lane * 4);
        uint4 r2 = *(const uint4*)(g_hh + (size_t)s2 * 128 + lane * 4);
        uint4 r3 = *(const uint4*)(g_hh + (size_t)s3 * 128 + lane * 4);
        agg_edge1(as0, r0, advh, a, den);
        agg_edge1(as1, r1, advh, a, den);
        agg_edge1(as2, r2, advh, a, den);
        agg_edge1(as3, r3, advh, a, den);
    }
    for (; p < end; p++) {
        int s = g_csrc[p];
        float asv = g_as[s * 4 + head];
        uint4 r = *(const uint4*)(g_hh + (size_t)s * 128 + lane * 4);
        agg_edge1(asv, r, advh, a, den);
    }

    float inv = 1.f / den;
    int colb = lane * 8;
    const float4* bv = (const float4*)(bias + colb);
    float4 b0 = bv[0], b1 = bv[1];
    const float4* wv = (const float4*)(W2 + colb);
    float4 w0 = wv[0], w1 = wv[1];
    float pr = 0.f, t;
    t = a[0] * inv + b0.x; t = t > 0.f ? t : expm1f(t); pr += t * w0.x;
    t = a[1] * inv + b0.y; t = t > 0.f ? t : expm1f(t); pr += t * w0.y;
    t = a[2] * inv + b0.z; t = t > 0.f ? t : expm1f(t); pr += t * w0.z;
    t = a[3] * inv + b0.w; t = t > 0.f ? t : expm1f(t); pr += t * w0.w;
    t = a[4] * inv + b1.x; t = t > 0.f ? t : expm1f(t); pr += t * w1.x;
    t = a[5] * inv + b1.y; t = t > 0.f ? t : expm1f(t); pr += t * w1.y;
    t = a[6] * inv + b1.z; t = t > 0.f ? t : expm1f(t); pr += t * w1.z;
    t = a[7] * inv + b1.w; t = t > 0.f ? t : expm1f(t); pr += t * w1.w;
#pragma unroll
    for (int o = 16; o; o >>= 1) pr += __shfl_xor_sync(0xFFFFFFFFu, pr, o);
    if (lane == 0) g_z[gw] = pr;
}

// ---------------- layer-2 softmax + aggregation (4 lanes per node) ----------------
__global__ void k_agg2(const float* __restrict__ att_s2,
                       const float* __restrict__ att_d2,
                       const float* __restrict__ bias2,
                       float* __restrict__ out) {
    int lane = threadIdx.x & 31;
    int sub = lane >> 2;          // node slot within warp (0..7)
    int li  = lane & 3;           // lane within node group
    int gw = ((blockIdx.x * blockDim.x + threadIdx.x) >> 5) * 8 + sub;
    if (gw >= NN) return;
    float atts = att_s2[0], attd = att_d2[0];
    int beg = gw * CAP;
    int end = beg + g_deg[gw];
    float adv = g_z[gw] * attd;

    float den = 0.f, acc = 0.f;
    for (int p = beg + li; p < end; p += 4) {
        int s = g_csrc[p];
        float zs = g_z[s];
        float w = __expf(leaky(zs * atts + adv));
        den += w;
        acc += w * zs;
    }
#pragma unroll
    for (int o = 1; o <= 2; o <<= 1) {
        den += __shfl_xor_sync(0xFFFFFFFFu, den, o);
        acc += __shfl_xor_sync(0xFFFFFFFFu, acc, o);
    }
    if (li == 0) out[gw] = acc / den + bias2[0];
}

// ---------------- launch (single stream; scatter fused into gemm) ----------------
extern "C" void kernel_launch(void* const* d_in, const int* in_sizes, int n_in,
                              void* d_out, int out_size) {
    const float* x     = (const float*)d_in[0];
    const int*   ei    = (const int*)d_in[1];
    const float* W1    = (const float*)d_in[2];
    const float* atts1 = (const float*)d_in[3];
    const float* attd1 = (const float*)d_in[4];
    const float* bias1 = (const float*)d_in[5];
    const float* W2    = (const float*)d_in[6];
    const float* atts2 = (const float*)d_in[7];
    const float* attd2 = (const float*)d_in[8];
    const float* bias2 = (const float*)d_in[9];
    float* out = (float*)d_out;
    (void)in_sizes; (void)n_in; (void)out_size;

    cudaFuncSetAttribute(k_gemm_mma, cudaFuncAttributeMaxDynamicSharedMemorySize,
                         SMEM_TOTAL_GEMM);

    cudaMemsetAsync(g_deg_addr, 0, NN * sizeof(int), 0);
    k_gemm_mma<<<GEMM_GRID, 256, SMEM_TOTAL_GEMM>>>(x, ei, W1, atts1, attd1);

    int warp_blocks1 = (NN * 32 + 255) / 256;          // warp per node
    k_agg1<<<warp_blocks1, 256>>>(bias1, W2);
    int warp_blocks2 = ((NN + 7) / 8 * 32 + 255) / 256; // 8 nodes per warp
    k_agg2<<<warp_blocks2, 256>>>(atts2, attd2, bias2, out);
}